// round 14
// baseline (speedup 1.0000x reference)
#include <cuda_runtime.h>
#include <cuda_bf16.h>
#include <stdint.h>
#include <math.h>

#define S_LEN 2048
#define BATCH 2
#define DIMW  1024
#define NHEAD 16
#define HDIM  64
#define MROWS (BATCH * S_LEN)   /* 4096 */

/* GEMM tiling (mma.sync m16n8k16 bf16, 3-term split, ldmatrix) */
#define BM 128
#define BN 128
#define BK 32
#define PITCH 80                       /* smem row pitch: 64B data + 16B pad */
#define TILE_SZ (128 * PITCH)          /* 10240 */
#define STAGE_SZ (4 * TILE_SZ)         /* 40960: Ah,Al,Bh,Bl */
#define NSTAGE 3
#define SMEM_GEMM (NSTAGE * STAGE_SZ)  /* 122880 */
#define NSLAB (DIMW / BK)              /* 32 */

/* attention smem layout (dynamic) */
#define PK   144
#define PV   272
#define KH0  0
#define KL0  (128 * PK)
#define VH0  (2 * 128 * PK)
#define VL0  (VH0 + 64 * PV)
#define SMEM_ATTN (VL0 + 64 * PV)      /* 71680 */

/* Scratch (allocation-free rule: device globals) */
__device__ float g_q[MROWS * DIMW];
__device__ float g_k[MROWS * DIMW];
__device__ float g_v[MROWS * DIMW];
__device__ __nv_bfloat16 g_xh[MROWS * DIMW];
__device__ __nv_bfloat16 g_xl[MROWS * DIMW];
__device__ __nv_bfloat16 g_ah[MROWS * DIMW];
__device__ __nv_bfloat16 g_al[MROWS * DIMW];
__device__ __nv_bfloat16 g_wh[4 * DIMW * DIMW];
__device__ __nv_bfloat16 g_wl[4 * DIMW * DIMW];

/* ---------------- helpers ---------------- */
__device__ __forceinline__ uint32_t smem_u32(const void* p) {
    uint32_t a;
    asm("{ .reg .u64 t; cvta.to.shared.u64 t, %1; cvt.u32.u64 %0, t; }"
        : "=r"(a) : "l"(p));
    return a;
}
__device__ __forceinline__ void cp16(uint32_t dst, const void* src) {
    asm volatile("cp.async.cg.shared.global [%0], [%1], 16;"
                 :: "r"(dst), "l"(src) : "memory");
}
__device__ __forceinline__ void mma_bf16(float* d, const uint32_t* a,
                                         const uint32_t* b) {
    asm volatile(
        "mma.sync.aligned.m16n8k16.row.col.f32.bf16.bf16.f32 "
        "{%0,%1,%2,%3}, {%4,%5,%6,%7}, {%8,%9}, {%0,%1,%2,%3};"
        : "+f"(d[0]), "+f"(d[1]), "+f"(d[2]), "+f"(d[3])
        : "r"(a[0]), "r"(a[1]), "r"(a[2]), "r"(a[3]), "r"(b[0]), "r"(b[1]));
}
__device__ __forceinline__ void ldsm4(uint32_t* r, uint32_t addr) {
    asm volatile("ldmatrix.sync.aligned.m8n8.x4.shared.b16 {%0,%1,%2,%3}, [%4];"
                 : "=r"(r[0]), "=r"(r[1]), "=r"(r[2]), "=r"(r[3]) : "r"(addr));
}
__device__ __forceinline__ void split2(float x, float y,
                                       uint32_t& hi, uint32_t& lo) {
    __nv_bfloat16 hx = __float2bfloat16(x);
    __nv_bfloat16 hy = __float2bfloat16(y);
    __nv_bfloat16 lx = __float2bfloat16(x - __bfloat162float(hx));
    __nv_bfloat16 ly = __float2bfloat16(y - __bfloat162float(hy));
    __nv_bfloat162 h = __halves2bfloat162(hx, hy);
    __nv_bfloat162 l = __halves2bfloat162(lx, ly);
    hi = *reinterpret_cast<uint32_t*>(&h);
    lo = *reinterpret_cast<uint32_t*>(&l);
}

/* ---------------- fp32 -> bf16 hi/lo split ---------------- */
__global__ void __launch_bounds__(256) split_kernel(
        const float* __restrict__ s,
        __nv_bfloat16* __restrict__ dh,
        __nv_bfloat16* __restrict__ dl, int n4) {
    const int i = blockIdx.x * 256 + threadIdx.x;
    if (i >= n4) return;
    float4 v = ((const float4*)s)[i];
    uint32_t h0, l0, h1, l1;
    split2(v.x, v.y, h0, l0);
    split2(v.z, v.w, h1, l1);
    ((uint32_t*)dh)[2*i] = h0; ((uint32_t*)dh)[2*i+1] = h1;
    ((uint32_t*)dl)[2*i] = l0; ((uint32_t*)dl)[2*i+1] = l1;
}

/* ---------------- HMMA GEMM: C[M,N] = A*B^T + bias ---------------- */
__device__ void gemm_mma(const __nv_bfloat16* __restrict__ Ah,
                         const __nv_bfloat16* __restrict__ Al,
                         const __nv_bfloat16* __restrict__ Bh,
                         const __nv_bfloat16* __restrict__ Bl,
                         const float* __restrict__ bias,
                         float* __restrict__ C) {
    extern __shared__ char smem[];
    const uint32_t sb = smem_u32(smem);
    const int tid  = threadIdx.x;
    const int wid  = tid >> 5, lane = tid & 31;
    const int g    = lane >> 2, tig = lane & 3;
    const int wm   = (wid & 1) * 64;
    const int wn   = (wid >> 1) * 32;
    const int row0 = blockIdx.y * BM;
    const int col0 = blockIdx.x * BN;

    const __nv_bfloat16* srcs[4] = {
        Ah + (size_t)row0 * DIMW, Al + (size_t)row0 * DIMW,
        Bh + (size_t)col0 * DIMW, Bl + (size_t)col0 * DIMW };

    const int r0 = tid >> 2, cc0 = (tid & 3);
    const int r1 = (tid + 256) >> 2, cc1 = ((tid + 256) & 3);

#define LOAD_STAGE(s, stg) do {                                              \
        const int k0_ = (s) * BK;                                            \
        _Pragma("unroll")                                                    \
        for (int t_ = 0; t_ < 4; ++t_) {                                     \
            const __nv_bfloat16* b_ = srcs[t_];                              \
            const uint32_t d_ = sb + (stg) * STAGE_SZ + t_ * TILE_SZ;        \
            cp16(d_ + r0 * PITCH + cc0 * 16,                                 \
                 b_ + (size_t)r0 * DIMW + k0_ + cc0 * 8);                    \
            cp16(d_ + r1 * PITCH + cc1 * 16,                                 \
                 b_ + (size_t)r1 * DIMW + k0_ + cc1 * 8);                    \
        }                                                                    \
    } while (0)

    /* ldmatrix per-lane offsets (within a tile, bytes) */
    const int lrow = lane & 7, lm = lane >> 3;
    uint32_t offA[4], offB[2];
#pragma unroll
    for (int mi = 0; mi < 4; ++mi)
        offA[mi] = (uint32_t)((wm + mi * 16 + lrow + (lm & 1) * 8) * PITCH
                              + (lm >> 1) * 16);
#pragma unroll
    for (int np = 0; np < 2; ++np)
        offB[np] = (uint32_t)((wn + np * 16 + (lm >> 1) * 8 + lrow) * PITCH
                              + (lm & 1) * 16);

    float acc[4][4][4];
#pragma unroll
    for (int mi = 0; mi < 4; ++mi)
#pragma unroll
        for (int ni = 0; ni < 4; ++ni)
#pragma unroll
            for (int r = 0; r < 4; ++r) acc[mi][ni][r] = 0.f;

    LOAD_STAGE(0, 0);
    asm volatile("cp.async.commit_group;" ::: "memory");
    LOAD_STAGE(1, 1);
    asm volatile("cp.async.commit_group;" ::: "memory");

    for (int s = 0; s < NSLAB; ++s) {
        if (s + 1 < NSLAB) asm volatile("cp.async.wait_group 1;" ::: "memory");
        else               asm volatile("cp.async.wait_group 0;" ::: "memory");
        __syncthreads();                 /* stage s ready; stage s-1 consumed */

        if (s + 2 < NSLAB) {             /* refill the buffer freed at s-1 */
            LOAD_STAGE(s + 2, (s + 2) % NSTAGE);
            asm volatile("cp.async.commit_group;" ::: "memory");
        }

        const uint32_t st = sb + (uint32_t)((s % NSTAGE) * STAGE_SZ);
        const uint32_t tAh = st;
        const uint32_t tAl = st + TILE_SZ;
        const uint32_t tBh = st + 2 * TILE_SZ;
        const uint32_t tBl = st + 3 * TILE_SZ;

#pragma unroll
        for (int ks = 0; ks < 2; ++ks) {
            const uint32_t kofs = ks * 32;
            uint32_t bh[8], bl[8];
            ldsm4(bh,     tBh + offB[0] + kofs);
            ldsm4(bh + 4, tBh + offB[1] + kofs);
            ldsm4(bl,     tBl + offB[0] + kofs);
            ldsm4(bl + 4, tBl + offB[1] + kofs);
#pragma unroll
            for (int mi = 0; mi < 4; ++mi) {
                uint32_t ah[4], al[4];
                ldsm4(ah, tAh + offA[mi] + kofs);
                ldsm4(al, tAl + offA[mi] + kofs);
#pragma unroll
                for (int ni = 0; ni < 4; ++ni) {
                    mma_bf16(acc[mi][ni], ah, bh + ni * 2);
                    mma_bf16(acc[mi][ni], ah, bl + ni * 2);
                    mma_bf16(acc[mi][ni], al, bh + ni * 2);
                }
            }
        }
    }

    /* epilogue: + bias -> C */
#pragma unroll
    for (int ni = 0; ni < 4; ++ni) {
        const int cc = col0 + wn + ni * 8 + tig * 2;
        const float b0 = bias[cc], b1 = bias[cc + 1];
#pragma unroll
        for (int mi = 0; mi < 4; ++mi) {
            const int rr = row0 + wm + mi * 16 + g;
            float2 v0, v1;
            v0.x = acc[mi][ni][0] + b0; v0.y = acc[mi][ni][1] + b1;
            v1.x = acc[mi][ni][2] + b0; v1.y = acc[mi][ni][3] + b1;
            *(float2*)(C + (size_t)rr * DIMW + cc) = v0;
            *(float2*)(C + (size_t)(rr + 8) * DIMW + cc) = v1;
        }
    }
#undef LOAD_STAGE
}

__global__ void __launch_bounds__(256) qkv_tc_kernel(
        const float* __restrict__ bq, const float* __restrict__ bk,
        const float* __restrict__ bv) {
    const int z = blockIdx.z;
    const __nv_bfloat16* Bh = g_wh + (size_t)z * DIMW * DIMW;
    const __nv_bfloat16* Bl = g_wl + (size_t)z * DIMW * DIMW;
    const float* bias = (z == 0) ? bq : (z == 1) ? bk : bv;
    float* C = (z == 0) ? g_q : (z == 1) ? g_k : g_v;
    gemm_mma(g_xh, g_xl, Bh, Bl, bias, C);
}

__global__ void __launch_bounds__(256) out_tc_kernel(
        const float* __restrict__ bo, float* __restrict__ out) {
    gemm_mma(g_ah, g_al, g_wh + (size_t)3 * DIMW * DIMW,
             g_wl + (size_t)3 * DIMW * DIMW, bo, out);
}

/* ---------------- RMSNorm + interleaved RoPE (in place) ---------------- */
__global__ void __launch_bounds__(256) normrope_kernel(
        const float* __restrict__ freqs,
        const float* __restrict__ qw, const float* __restrict__ kw) {
    const int lane = threadIdx.x & 31;
    const int warp = threadIdx.x >> 5;
    const unsigned rowIdx = blockIdx.x * 8u + warp;
    float*       base = (blockIdx.y == 0) ? g_q : g_k;
    const float* w    = (blockIdx.y == 0) ? qw : kw;

    const unsigned bs = rowIdx >> 4;
    const unsigned h  = rowIdx & 15;
    const unsigned s  = bs & (S_LEN - 1);

    float* p = base + (size_t)bs * DIMW + h * HDIM + 2 * lane;
    float2 xv = *(const float2*)p;

    float ss = xv.x * xv.x + xv.y * xv.y;
#pragma unroll
    for (int off = 16; off; off >>= 1)
        ss += __shfl_xor_sync(0xffffffffu, ss, off);
    const float r = rsqrtf(ss * (1.0f / 64.0f) + 1e-6f);

    const float n0 = xv.x * r * w[2 * lane];
    const float n1 = xv.y * r * w[2 * lane + 1];

    const float f = freqs[(size_t)s * HDIM + 2 * lane];
    float sn, c;
    sincosf(f, &sn, &c);

    float2 o;
    o.x = n0 * c - n1 * sn;
    o.y = n1 * c + n0 * sn;
    *(float2*)p = o;
}

/* ---------------- HMMA chunked attention ---------------- */
__global__ void __launch_bounds__(256) attn_kernel() {
    extern __shared__ char sm[];
    const int qc  = blockIdx.x;
    const int h   = blockIdx.y;
    const int b   = blockIdx.z;
    const int tid = threadIdx.x;
    const int wid = tid >> 5, lane = tid & 31;
    const int g   = lane >> 2, tig = lane & 3;
    const int wm  = wid * 16;

    const float* qbase = g_q + ((size_t)(b * S_LEN + qc * 128)) * DIMW + h * HDIM;
    uint32_t qh[4][4], ql[4][4];
#pragma unroll
    for (int t = 0; t < 4; ++t) {
        const float* p0 = qbase + (size_t)(wm + g) * DIMW + t * 16 + 2 * tig;
        const float* p1 = qbase + (size_t)(wm + g + 8) * DIMW + t * 16 + 2 * tig;
        float2 v;
        v = *(const float2*)p0;       split2(v.x, v.y, qh[t][0], ql[t][0]);
        v = *(const float2*)p1;       split2(v.x, v.y, qh[t][1], ql[t][1]);
        v = *(const float2*)(p0 + 8); split2(v.x, v.y, qh[t][2], ql[t][2]);
        v = *(const float2*)(p1 + 8); split2(v.x, v.y, qh[t][3], ql[t][3]);
    }

    float O[8][4];
#pragma unroll
    for (int dt = 0; dt < 8; ++dt)
#pragma unroll
        for (int r = 0; r < 4; ++r) O[dt][r] = 0.f;
    float l0 = 0.f, l1 = 0.f;

    int kcs[6];
    int nkc = 0;
    kcs[nkc++] = qc;
    if (qc >= 9) {
        int lo = qc - 13; if (lo < 0) lo = 0;
        for (int ck = lo; ck <= qc - 9; ++ck) kcs[nkc++] = ck;
    }

    for (int ci = 0; ci < nkc; ++ci) {
        const size_t krow0 = (size_t)b * S_LEN + kcs[ci] * 128;
        const float* kb = g_k + krow0 * DIMW + h * HDIM;
        const float* vb = g_v + krow0 * DIMW + h * HDIM;

        __syncthreads();
#pragma unroll
        for (int i = 0; i < 8; ++i) {
            const int idx = tid + 256 * i;
            const int j = idx >> 4, dc = (idx & 15) * 4;
            float4 v = *(const float4*)(kb + (size_t)j * DIMW + dc);
            uint2 hh, ll;
            split2(v.x, v.y, hh.x, ll.x);
            split2(v.z, v.w, hh.y, ll.y);
            *(uint2*)(sm + KH0 + j * PK + dc * 2) = hh;
            *(uint2*)(sm + KL0 + j * PK + dc * 2) = ll;
        }
#pragma unroll
        for (int i = 0; i < 8; ++i) {
            const int idx = tid + 256 * i;
            const int j = idx >> 4, dc = (idx & 15) * 4;
            float4 v = *(const float4*)(vb + (size_t)j * DIMW + dc);
            const float vv[4] = {v.x, v.y, v.z, v.w};
#pragma unroll
            for (int e = 0; e < 4; ++e) {
                const int d = dc + e;
                __nv_bfloat16 hb = __float2bfloat16(vv[e]);
                __nv_bfloat16 lb = __float2bfloat16(vv[e] - __bfloat162float(hb));
                *(__nv_bfloat16*)(sm + VH0 + d * PV + j * 2) = hb;
                *(__nv_bfloat16*)(sm + VL0 + d * PV + j * 2) = lb;
            }
        }
        __syncthreads();

        float S[16][4];
#pragma unroll
        for (int nt = 0; nt < 16; ++nt) {
            S[nt][0] = S[nt][1] = S[nt][2] = S[nt][3] = 0.f;
            const int jr = nt * 8 + g;
            uint32_t kh[4][2], kl[4][2];
#pragma unroll
            for (int t = 0; t < 4; ++t) {
                const int ofs = jr * PK + t * 32 + tig * 4;
                kh[t][0] = *(const uint32_t*)(sm + KH0 + ofs);
                kh[t][1] = *(const uint32_t*)(sm + KH0 + ofs + 16);
                kl[t][0] = *(const uint32_t*)(sm + KL0 + ofs);
                kl[t][1] = *(const uint32_t*)(sm + KL0 + ofs + 16);
            }
#pragma unroll
            for (int t = 0; t < 4; ++t) {
                mma_bf16(S[nt], qh[t], kh[t]);
                mma_bf16(S[nt], qh[t], kl[t]);
                mma_bf16(S[nt], ql[t], kh[t]);
            }
        }

        float rs0 = 0.f, rs1 = 0.f;
#pragma unroll
        for (int nt = 0; nt < 16; ++nt) {
            S[nt][0] = __expf(S[nt][0] * 0.125f);
            S[nt][1] = __expf(S[nt][1] * 0.125f);
            S[nt][2] = __expf(S[nt][2] * 0.125f);
            S[nt][3] = __expf(S[nt][3] * 0.125f);
            rs0 += S[nt][0] + S[nt][1];
            rs1 += S[nt][2] + S[nt][3];
        }
        rs0 += __shfl_xor_sync(0xffffffffu, rs0, 1);
        rs0 += __shfl_xor_sync(0xffffffffu, rs0, 2);
        rs1 += __shfl_xor_sync(0xffffffffu, rs1, 1);
        rs1 += __shfl_xor_sync(0xffffffffu, rs1, 2);
        l0 += rs0;
        l1 += rs1;

#pragma unroll
        for (int tp = 0; tp < 8; ++tp) {
            uint32_t ah[4], al[4];
            split2(S[2*tp][0],   S[2*tp][1],   ah[0], al[0]);
            split2(S[2*tp][2],   S[2*tp][3],   ah[1], al[1]);
            split2(S[2*tp+1][0], S[2*tp+1][1], ah[2], al[2]);
            split2(S[2*tp+1][2], S[2*tp+1][3], ah[3], al[3]);
#pragma unroll
            for (int dt = 0; dt < 8; ++dt) {
                const int ofs = (dt * 8 + g) * PV + tp * 32 + tig * 4;
                uint32_t bh[2], bl[2];
                bh[0] = *(const uint32_t*)(sm + VH0 + ofs);
                bh[1] = *(const uint32_t*)(sm + VH0 + ofs + 16);
                bl[0] = *(const uint32_t*)(sm + VL0 + ofs);
                bl[1] = *(const uint32_t*)(sm + VL0 + ofs + 16);
                mma_bf16(O[dt], ah, bh);
                mma_bf16(O[dt], ah, bl);
                mma_bf16(O[dt], al, bh);
            }
        }
    }

    const float il0 = 1.f / l0, il1 = 1.f / l1;
    const size_t row0 = (size_t)b * S_LEN + qc * 128 + wm + g;
    const size_t base0 = row0 * DIMW + h * HDIM;
    const size_t base1 = (row0 + 8) * DIMW + h * HDIM;
#pragma unroll
    for (int dt = 0; dt < 8; ++dt) {
        const int d = dt * 8 + 2 * tig;
        uint32_t hh, ll;
        split2(O[dt][0] * il0, O[dt][1] * il0, hh, ll);
        *(uint32_t*)(g_ah + base0 + d) = hh;
        *(uint32_t*)(g_al + base0 + d) = ll;
        split2(O[dt][2] * il1, O[dt][3] * il1, hh, ll);
        *(uint32_t*)(g_ah + base1 + d) = hh;
        *(uint32_t*)(g_al + base1 + d) = ll;
    }
}

/* ------------------------------------------------------------------ */
extern "C" void kernel_launch(void* const* d_in, const int* in_sizes, int n_in,
                              void* d_out, int out_size) {
    const float* x     = (const float*)d_in[0];
    const float* freqs = (const float*)d_in[2];
    const float* Wq    = (const float*)d_in[3];
    const float* bq    = (const float*)d_in[4];
    const float* Wk    = (const float*)d_in[5];
    const float* bk    = (const float*)d_in[6];
    const float* Wv    = (const float*)d_in[7];
    const float* bv    = (const float*)d_in[8];
    const float* Wo    = (const float*)d_in[9];
    const float* bo    = (const float*)d_in[10];
    const float* qw    = (const float*)d_in[11];
    const float* kw    = (const float*)d_in[12];
    float* out = (float*)d_out;

    cudaFuncSetAttribute(qkv_tc_kernel,
                         cudaFuncAttributeMaxDynamicSharedMemorySize, SMEM_GEMM);
    cudaFuncSetAttribute(out_tc_kernel,
                         cudaFuncAttributeMaxDynamicSharedMemorySize, SMEM_GEMM);
    cudaFuncSetAttribute(attn_kernel,
                         cudaFuncAttributeMaxDynamicSharedMemorySize, SMEM_ATTN);

    __nv_bfloat16 *xh, *xl, *wh, *wl;
    cudaGetSymbolAddress((void**)&xh, g_xh);
    cudaGetSymbolAddress((void**)&xl, g_xl);
    cudaGetSymbolAddress((void**)&wh, g_wh);
    cudaGetSymbolAddress((void**)&wl, g_wl);

    const int WN = DIMW * DIMW;          /* 1048576 */
    split_kernel<<<(MROWS * DIMW / 4 + 255) / 256, 256>>>(x, xh, xl, MROWS * DIMW / 4);
    split_kernel<<<(WN / 4 + 255) / 256, 256>>>(Wq, wh + 0 * (size_t)WN, wl + 0 * (size_t)WN, WN / 4);
    split_kernel<<<(WN / 4 + 255) / 256, 256>>>(Wk, wh + 1 * (size_t)WN, wl + 1 * (size_t)WN, WN / 4);
    split_kernel<<<(WN / 4 + 255) / 256, 256>>>(Wv, wh + 2 * (size_t)WN, wl + 2 * (size_t)WN, WN / 4);
    split_kernel<<<(WN / 4 + 255) / 256, 256>>>(Wo, wh + 3 * (size_t)WN, wl + 3 * (size_t)WN, WN / 4);

    qkv_tc_kernel<<<dim3(DIMW / BN, MROWS / BM, 3), 256, SMEM_GEMM>>>(bq, bk, bv);
    normrope_kernel<<<dim3((MROWS * NHEAD) / 8, 2), 256>>>(freqs, qw, kw);
    attn_kernel<<<dim3(16, NHEAD, BATCH), 256, SMEM_ATTN>>>();
    out_tc_kernel<<<dim3(DIMW / BN, MROWS / BM), 256, SMEM_GEMM>>>(bo, out);
}

// round 15
// speedup vs baseline: 1.0161x; 1.0161x over previous
#include <cuda_runtime.h>
#include <cuda_bf16.h>
#include <stdint.h>
#include <math.h>

#define S_LEN 2048
#define BATCH 2
#define DIMW  1024
#define NHEAD 16
#define HDIM  64
#define MROWS (BATCH * S_LEN)   /* 4096 */

/* GEMM tiling (mma.sync m16n8k16 bf16, 3-term split, ldmatrix) */
#define BM 128
#define BN 128
#define BK 32
#define PITCH 80                       /* smem row pitch: 64B data + 16B pad */
#define TILE_SZ (128 * PITCH)          /* 10240 */
#define STAGE_SZ (4 * TILE_SZ)         /* 40960: Ah,Al,Bh,Bl */
#define SMEM_GEMM (2 * STAGE_SZ)       /* 81920 -> 2 CTAs/SM */
#define NSLAB (DIMW / BK)              /* 32 */

/* attention smem layout (dynamic) */
#define PK   144
#define PV   272
#define KH0  0
#define KL0  (128 * PK)
#define VH0  (2 * 128 * PK)
#define VL0  (VH0 + 64 * PV)
#define SMEM_ATTN (VL0 + 64 * PV)      /* 71680 */

/* Scratch (allocation-free rule: device globals) */
__device__ float g_q[MROWS * DIMW];
__device__ float g_k[MROWS * DIMW];
__device__ float g_v[MROWS * DIMW];
__device__ __nv_bfloat16 g_xh[MROWS * DIMW];
__device__ __nv_bfloat16 g_xl[MROWS * DIMW];
__device__ __nv_bfloat16 g_ah[MROWS * DIMW];
__device__ __nv_bfloat16 g_al[MROWS * DIMW];
__device__ __nv_bfloat16 g_wh[4 * DIMW * DIMW];
__device__ __nv_bfloat16 g_wl[4 * DIMW * DIMW];

/* ---------------- helpers ---------------- */
__device__ __forceinline__ uint32_t smem_u32(const void* p) {
    uint32_t a;
    asm("{ .reg .u64 t; cvta.to.shared.u64 t, %1; cvt.u32.u64 %0, t; }"
        : "=r"(a) : "l"(p));
    return a;
}
__device__ __forceinline__ void cp16(uint32_t dst, const void* src) {
    asm volatile("cp.async.cg.shared.global [%0], [%1], 16;"
                 :: "r"(dst), "l"(src) : "memory");
}
__device__ __forceinline__ void mma_bf16(float* d, const uint32_t* a,
                                         const uint32_t* b) {
    asm volatile(
        "mma.sync.aligned.m16n8k16.row.col.f32.bf16.bf16.f32 "
        "{%0,%1,%2,%3}, {%4,%5,%6,%7}, {%8,%9}, {%0,%1,%2,%3};"
        : "+f"(d[0]), "+f"(d[1]), "+f"(d[2]), "+f"(d[3])
        : "r"(a[0]), "r"(a[1]), "r"(a[2]), "r"(a[3]), "r"(b[0]), "r"(b[1]));
}
__device__ __forceinline__ void ldsm4(uint32_t* r, uint32_t addr) {
    asm volatile("ldmatrix.sync.aligned.m8n8.x4.shared.b16 {%0,%1,%2,%3}, [%4];"
                 : "=r"(r[0]), "=r"(r[1]), "=r"(r[2]), "=r"(r[3]) : "r"(addr));
}
__device__ __forceinline__ void split2(float x, float y,
                                       uint32_t& hi, uint32_t& lo) {
    __nv_bfloat16 hx = __float2bfloat16(x);
    __nv_bfloat16 hy = __float2bfloat16(y);
    __nv_bfloat16 lx = __float2bfloat16(x - __bfloat162float(hx));
    __nv_bfloat16 ly = __float2bfloat16(y - __bfloat162float(hy));
    __nv_bfloat162 h = __halves2bfloat162(hx, hy);
    __nv_bfloat162 l = __halves2bfloat162(lx, ly);
    hi = *reinterpret_cast<uint32_t*>(&h);
    lo = *reinterpret_cast<uint32_t*>(&l);
}

/* ---------------- fp32 -> bf16 hi/lo split ---------------- */
__global__ void __launch_bounds__(256) split_kernel(
        const float* __restrict__ s,
        __nv_bfloat16* __restrict__ dh,
        __nv_bfloat16* __restrict__ dl, int n4) {
    const int i = blockIdx.x * 256 + threadIdx.x;
    if (i >= n4) return;
    float4 v = ((const float4*)s)[i];
    uint32_t h0, l0, h1, l1;
    split2(v.x, v.y, h0, l0);
    split2(v.z, v.w, h1, l1);
    ((uint32_t*)dh)[2*i] = h0; ((uint32_t*)dh)[2*i+1] = h1;
    ((uint32_t*)dl)[2*i] = l0; ((uint32_t*)dl)[2*i+1] = l1;
}

/* ---------------- HMMA GEMM: C[M,N] = A*B^T + bias ---------------- */
__device__ void gemm_mma(const __nv_bfloat16* __restrict__ Ah,
                         const __nv_bfloat16* __restrict__ Al,
                         const __nv_bfloat16* __restrict__ Bh,
                         const __nv_bfloat16* __restrict__ Bl,
                         const float* __restrict__ bias,
                         float* __restrict__ C) {
    extern __shared__ char smem[];
    const uint32_t sb = smem_u32(smem);
    const int tid  = threadIdx.x;
    const int wid  = tid >> 5, lane = tid & 31;
    const int g    = lane >> 2, tig = lane & 3;
    const int wm   = (wid & 1) * 64;
    const int wn   = (wid >> 1) * 32;
    const int row0 = blockIdx.y * BM;
    const int col0 = blockIdx.x * BN;

    const __nv_bfloat16* srcs[4] = {
        Ah + (size_t)row0 * DIMW, Al + (size_t)row0 * DIMW,
        Bh + (size_t)col0 * DIMW, Bl + (size_t)col0 * DIMW };

    const int r0 = tid >> 2, cc0 = (tid & 3);
    const int r1 = (tid + 256) >> 2, cc1 = ((tid + 256) & 3);

#define LOAD_STAGE(s, stg) do {                                              \
        const int k0_ = (s) * BK;                                            \
        _Pragma("unroll")                                                    \
        for (int t_ = 0; t_ < 4; ++t_) {                                     \
            const __nv_bfloat16* b_ = srcs[t_];                              \
            const uint32_t d_ = sb + (stg) * STAGE_SZ + t_ * TILE_SZ;        \
            cp16(d_ + r0 * PITCH + cc0 * 16,                                 \
                 b_ + (size_t)r0 * DIMW + k0_ + cc0 * 8);                    \
            cp16(d_ + r1 * PITCH + cc1 * 16,                                 \
                 b_ + (size_t)r1 * DIMW + k0_ + cc1 * 8);                    \
        }                                                                    \
    } while (0)

    /* ldmatrix per-lane offsets (within a tile, bytes) */
    const int lrow = lane & 7, lm = lane >> 3;
    uint32_t offA[4], offB[2];
#pragma unroll
    for (int mi = 0; mi < 4; ++mi)
        offA[mi] = (uint32_t)((wm + mi * 16 + lrow + (lm & 1) * 8) * PITCH
                              + (lm >> 1) * 16);
#pragma unroll
    for (int np = 0; np < 2; ++np)
        offB[np] = (uint32_t)((wn + np * 16 + (lm >> 1) * 8 + lrow) * PITCH
                              + (lm & 1) * 16);

    float acc[4][4][4];
#pragma unroll
    for (int mi = 0; mi < 4; ++mi)
#pragma unroll
        for (int ni = 0; ni < 4; ++ni)
#pragma unroll
            for (int r = 0; r < 4; ++r) acc[mi][ni][r] = 0.f;

    LOAD_STAGE(0, 0);
    asm volatile("cp.async.commit_group;" ::: "memory");

    for (int s = 0; s < NSLAB; ++s) {
        const int cur = s & 1;
        if (s + 1 < NSLAB) {
            LOAD_STAGE(s + 1, cur ^ 1);
            asm volatile("cp.async.commit_group;" ::: "memory");
            asm volatile("cp.async.wait_group 1;" ::: "memory");
        } else {
            asm volatile("cp.async.wait_group 0;" ::: "memory");
        }
        __syncthreads();

        const uint32_t st = sb + (uint32_t)(cur * STAGE_SZ);
        const uint32_t tAh = st;
        const uint32_t tAl = st + TILE_SZ;
        const uint32_t tBh = st + 2 * TILE_SZ;
        const uint32_t tBl = st + 3 * TILE_SZ;

#pragma unroll
        for (int ks = 0; ks < 2; ++ks) {
            const uint32_t kofs = ks * 32;
            uint32_t bh[8], bl[8];
            ldsm4(bh,     tBh + offB[0] + kofs);
            ldsm4(bh + 4, tBh + offB[1] + kofs);
            ldsm4(bl,     tBl + offB[0] + kofs);
            ldsm4(bl + 4, tBl + offB[1] + kofs);
#pragma unroll
            for (int mi = 0; mi < 4; ++mi) {
                uint32_t ah[4], al[4];
                ldsm4(ah, tAh + offA[mi] + kofs);
                ldsm4(al, tAl + offA[mi] + kofs);
#pragma unroll
                for (int ni = 0; ni < 4; ++ni) {
                    mma_bf16(acc[mi][ni], ah, bh + ni * 2);
                    mma_bf16(acc[mi][ni], ah, bl + ni * 2);
                    mma_bf16(acc[mi][ni], al, bh + ni * 2);
                }
            }
        }
        __syncthreads();
    }

    /* epilogue: + bias -> C */
#pragma unroll
    for (int ni = 0; ni < 4; ++ni) {
        const int cc = col0 + wn + ni * 8 + tig * 2;
        const float b0 = bias[cc], b1 = bias[cc + 1];
#pragma unroll
        for (int mi = 0; mi < 4; ++mi) {
            const int rr = row0 + wm + mi * 16 + g;
            float2 v0, v1;
            v0.x = acc[mi][ni][0] + b0; v0.y = acc[mi][ni][1] + b1;
            v1.x = acc[mi][ni][2] + b0; v1.y = acc[mi][ni][3] + b1;
            *(float2*)(C + (size_t)rr * DIMW + cc) = v0;
            *(float2*)(C + (size_t)(rr + 8) * DIMW + cc) = v1;
        }
    }
#undef LOAD_STAGE
}

__global__ void __launch_bounds__(256) qkv_tc_kernel(
        const float* __restrict__ bq, const float* __restrict__ bk,
        const float* __restrict__ bv) {
    const int z = blockIdx.z;
    const __nv_bfloat16* Bh = g_wh + (size_t)z * DIMW * DIMW;
    const __nv_bfloat16* Bl = g_wl + (size_t)z * DIMW * DIMW;
    const float* bias = (z == 0) ? bq : (z == 1) ? bk : bv;
    float* C = (z == 0) ? g_q : (z == 1) ? g_k : g_v;
    gemm_mma(g_xh, g_xl, Bh, Bl, bias, C);
}

__global__ void __launch_bounds__(256) out_tc_kernel(
        const float* __restrict__ bo, float* __restrict__ out) {
    gemm_mma(g_ah, g_al, g_wh + (size_t)3 * DIMW * DIMW,
             g_wl + (size_t)3 * DIMW * DIMW, bo, out);
}

/* ---------------- RMSNorm + interleaved RoPE (in place) ---------------- */
__global__ void __launch_bounds__(256) normrope_kernel(
        const float* __restrict__ freqs,
        const float* __restrict__ qw, const float* __restrict__ kw) {
    const int lane = threadIdx.x & 31;
    const int warp = threadIdx.x >> 5;
    const unsigned rowIdx = blockIdx.x * 8u + warp;
    float*       base = (blockIdx.y == 0) ? g_q : g_k;
    const float* w    = (blockIdx.y == 0) ? qw : kw;

    const unsigned bs = rowIdx >> 4;
    const unsigned h  = rowIdx & 15;
    const unsigned s  = bs & (S_LEN - 1);

    float* p = base + (size_t)bs * DIMW + h * HDIM + 2 * lane;
    float2 xv = *(const float2*)p;

    float ss = xv.x * xv.x + xv.y * xv.y;
#pragma unroll
    for (int off = 16; off; off >>= 1)
        ss += __shfl_xor_sync(0xffffffffu, ss, off);
    const float r = rsqrtf(ss * (1.0f / 64.0f) + 1e-6f);

    const float n0 = xv.x * r * w[2 * lane];
    const float n1 = xv.y * r * w[2 * lane + 1];

    const float f = freqs[(size_t)s * HDIM + 2 * lane];
    float sn, c;
    sincosf(f, &sn, &c);

    float2 o;
    o.x = n0 * c - n1 * sn;
    o.y = n1 * c + n0 * sn;
    *(float2*)p = o;
}

/* ---------------- HMMA chunked attention ---------------- */
__global__ void __launch_bounds__(256) attn_kernel() {
    extern __shared__ char sm[];
    const int qc  = blockIdx.x;
    const int h   = blockIdx.y;
    const int b   = blockIdx.z;
    const int tid = threadIdx.x;
    const int wid = tid >> 5, lane = tid & 31;
    const int g   = lane >> 2, tig = lane & 3;
    const int wm  = wid * 16;

    const float* qbase = g_q + ((size_t)(b * S_LEN + qc * 128)) * DIMW + h * HDIM;
    uint32_t qh[4][4], ql[4][4];
#pragma unroll
    for (int t = 0; t < 4; ++t) {
        const float* p0 = qbase + (size_t)(wm + g) * DIMW + t * 16 + 2 * tig;
        const float* p1 = qbase + (size_t)(wm + g + 8) * DIMW + t * 16 + 2 * tig;
        float2 v;
        v = *(const float2*)p0;       split2(v.x, v.y, qh[t][0], ql[t][0]);
        v = *(const float2*)p1;       split2(v.x, v.y, qh[t][1], ql[t][1]);
        v = *(const float2*)(p0 + 8); split2(v.x, v.y, qh[t][2], ql[t][2]);
        v = *(const float2*)(p1 + 8); split2(v.x, v.y, qh[t][3], ql[t][3]);
    }

    float O[8][4];
#pragma unroll
    for (int dt = 0; dt < 8; ++dt)
#pragma unroll
        for (int r = 0; r < 4; ++r) O[dt][r] = 0.f;
    float l0 = 0.f, l1 = 0.f;

    int kcs[6];
    int nkc = 0;
    kcs[nkc++] = qc;
    if (qc >= 9) {
        int lo = qc - 13; if (lo < 0) lo = 0;
        for (int ck = lo; ck <= qc - 9; ++ck) kcs[nkc++] = ck;
    }

    for (int ci = 0; ci < nkc; ++ci) {
        const size_t krow0 = (size_t)b * S_LEN + kcs[ci] * 128;
        const float* kb = g_k + krow0 * DIMW + h * HDIM;
        const float* vb = g_v + krow0 * DIMW + h * HDIM;

        __syncthreads();
#pragma unroll
        for (int i = 0; i < 8; ++i) {
            const int idx = tid + 256 * i;
            const int j = idx >> 4, dc = (idx & 15) * 4;
            float4 v = *(const float4*)(kb + (size_t)j * DIMW + dc);
            uint2 hh, ll;
            split2(v.x, v.y, hh.x, ll.x);
            split2(v.z, v.w, hh.y, ll.y);
            *(uint2*)(sm + KH0 + j * PK + dc * 2) = hh;
            *(uint2*)(sm + KL0 + j * PK + dc * 2) = ll;
        }
#pragma unroll
        for (int i = 0; i < 8; ++i) {
            const int idx = tid + 256 * i;
            const int j = idx >> 4, dc = (idx & 15) * 4;
            float4 v = *(const float4*)(vb + (size_t)j * DIMW + dc);
            const float vv[4] = {v.x, v.y, v.z, v.w};
#pragma unroll
            for (int e = 0; e < 4; ++e) {
                const int d = dc + e;
                __nv_bfloat16 hb = __float2bfloat16(vv[e]);
                __nv_bfloat16 lb = __float2bfloat16(vv[e] - __bfloat162float(hb));
                *(__nv_bfloat16*)(sm + VH0 + d * PV + j * 2) = hb;
                *(__nv_bfloat16*)(sm + VL0 + d * PV + j * 2) = lb;
            }
        }
        __syncthreads();

        float S[16][4];
#pragma unroll
        for (int nt = 0; nt < 16; ++nt) {
            S[nt][0] = S[nt][1] = S[nt][2] = S[nt][3] = 0.f;
            const int jr = nt * 8 + g;
            uint32_t kh[4][2], kl[4][2];
#pragma unroll
            for (int t = 0; t < 4; ++t) {
                const int ofs = jr * PK + t * 32 + tig * 4;
                kh[t][0] = *(const uint32_t*)(sm + KH0 + ofs);
                kh[t][1] = *(const uint32_t*)(sm + KH0 + ofs + 16);
                kl[t][0] = *(const uint32_t*)(sm + KL0 + ofs);
                kl[t][1] = *(const uint32_t*)(sm + KL0 + ofs + 16);
            }
#pragma unroll
            for (int t = 0; t < 4; ++t) {
                mma_bf16(S[nt], qh[t], kh[t]);
                mma_bf16(S[nt], qh[t], kl[t]);
                mma_bf16(S[nt], ql[t], kh[t]);
            }
        }

        float rs0 = 0.f, rs1 = 0.f;
#pragma unroll
        for (int nt = 0; nt < 16; ++nt) {
            S[nt][0] = __expf(S[nt][0] * 0.125f);
            S[nt][1] = __expf(S[nt][1] * 0.125f);
            S[nt][2] = __expf(S[nt][2] * 0.125f);
            S[nt][3] = __expf(S[nt][3] * 0.125f);
            rs0 += S[nt][0] + S[nt][1];
            rs1 += S[nt][2] + S[nt][3];
        }
        rs0 += __shfl_xor_sync(0xffffffffu, rs0, 1);
        rs0 += __shfl_xor_sync(0xffffffffu, rs0, 2);
        rs1 += __shfl_xor_sync(0xffffffffu, rs1, 1);
        rs1 += __shfl_xor_sync(0xffffffffu, rs1, 2);
        l0 += rs0;
        l1 += rs1;

#pragma unroll
        for (int tp = 0; tp < 8; ++tp) {
            uint32_t ah[4], al[4];
            split2(S[2*tp][0],   S[2*tp][1],   ah[0], al[0]);
            split2(S[2*tp][2],   S[2*tp][3],   ah[1], al[1]);
            split2(S[2*tp+1][0], S[2*tp+1][1], ah[2], al[2]);
            split2(S[2*tp+1][2], S[2*tp+1][3], ah[3], al[3]);
#pragma unroll
            for (int dt = 0; dt < 8; ++dt) {
                const int ofs = (dt * 8 + g) * PV + tp * 32 + tig * 4;
                uint32_t bh[2], bl[2];
                bh[0] = *(const uint32_t*)(sm + VH0 + ofs);
                bh[1] = *(const uint32_t*)(sm + VH0 + ofs + 16);
                bl[0] = *(const uint32_t*)(sm + VL0 + ofs);
                bl[1] = *(const uint32_t*)(sm + VL0 + ofs + 16);
                mma_bf16(O[dt], ah, bh);
                mma_bf16(O[dt], ah, bl);
                mma_bf16(O[dt], al, bh);
            }
        }
    }

    const float il0 = 1.f / l0, il1 = 1.f / l1;
    const size_t row0 = (size_t)b * S_LEN + qc * 128 + wm + g;
    const size_t base0 = row0 * DIMW + h * HDIM;
    const size_t base1 = (row0 + 8) * DIMW + h * HDIM;
#pragma unroll
    for (int dt = 0; dt < 8; ++dt) {
        const int d = dt * 8 + 2 * tig;
        uint32_t hh, ll;
        split2(O[dt][0] * il0, O[dt][1] * il0, hh, ll);
        *(uint32_t*)(g_ah + base0 + d) = hh;
        *(uint32_t*)(g_al + base0 + d) = ll;
        split2(O[dt][2] * il1, O[dt][3] * il1, hh, ll);
        *(uint32_t*)(g_ah + base1 + d) = hh;
        *(uint32_t*)(g_al + base1 + d) = ll;
    }
}

/* ------------------------------------------------------------------ */
extern "C" void kernel_launch(void* const* d_in, const int* in_sizes, int n_in,
                              void* d_out, int out_size) {
    const float* x     = (const float*)d_in[0];
    const float* freqs = (const float*)d_in[2];
    const float* Wq    = (const float*)d_in[3];
    const float* bq    = (const float*)d_in[4];
    const float* Wk    = (const float*)d_in[5];
    const float* bk    = (const float*)d_in[6];
    const float* Wv    = (const float*)d_in[7];
    const float* bv    = (const float*)d_in[8];
    const float* Wo    = (const float*)d_in[9];
    const float* bo    = (const float*)d_in[10];
    const float* qw    = (const float*)d_in[11];
    const float* kw    = (const float*)d_in[12];
    float* out = (float*)d_out;

    cudaFuncSetAttribute(qkv_tc_kernel,
                         cudaFuncAttributeMaxDynamicSharedMemorySize, SMEM_GEMM);
    cudaFuncSetAttribute(out_tc_kernel,
                         cudaFuncAttributeMaxDynamicSharedMemorySize, SMEM_GEMM);
    cudaFuncSetAttribute(attn_kernel,
                         cudaFuncAttributeMaxDynamicSharedMemorySize, SMEM_ATTN);

    __nv_bfloat16 *xh, *xl, *wh, *wl;
    cudaGetSymbolAddress((void**)&xh, g_xh);
    cudaGetSymbolAddress((void**)&xl, g_xl);
    cudaGetSymbolAddress((void**)&wh, g_wh);
    cudaGetSymbolAddress((void**)&wl, g_wl);

    const int WN = DIMW * DIMW;          /* 1048576 */
    split_kernel<<<(MROWS * DIMW / 4 + 255) / 256, 256>>>(x, xh, xl, MROWS * DIMW / 4);
    split_kernel<<<(WN / 4 + 255) / 256, 256>>>(Wq, wh + 0 * (size_t)WN, wl + 0 * (size_t)WN, WN / 4);
    split_kernel<<<(WN / 4 + 255) / 256, 256>>>(Wk, wh + 1 * (size_t)WN, wl + 1 * (size_t)WN, WN / 4);
    split_kernel<<<(WN / 4 + 255) / 256, 256>>>(Wv, wh + 2 * (size_t)WN, wl + 2 * (size_t)WN, WN / 4);
    split_kernel<<<(WN / 4 + 255) / 256, 256>>>(Wo, wh + 3 * (size_t)WN, wl + 3 * (size_t)WN, WN / 4);

    qkv_tc_kernel<<<dim3(DIMW / BN, MROWS / BM, 3), 256, SMEM_GEMM>>>(bq, bk, bv);
    normrope_kernel<<<dim3((MROWS * NHEAD) / 8, 2), 256>>>(freqs, qw, kw);
    attn_kernel<<<dim3(16, NHEAD, BATCH), 256, SMEM_ATTN>>>();
    out_tc_kernel<<<dim3(DIMW / BN, MROWS / BM), 256, SMEM_GEMM>>>(bo, out);
}

// round 16
// speedup vs baseline: 1.4663x; 1.4431x over previous
#include <cuda_runtime.h>
#include <cuda_fp16.h>
#include <stdint.h>
#include <math.h>

#define S_LEN 2048
#define BATCH 2
#define DIMW  1024
#define NHEAD 16
#define HDIM  64
#define MROWS (BATCH * S_LEN)   /* 4096 */

/* GEMM tiling (mma.sync m16n8k16 f16, 2-term split: (Ah+Al)*Bh) */
#define BM 128
#define BN 128
#define BK 32
#define PITCH 80                       /* smem row pitch: 64B data + 16B pad */
#define TILE_SZ (128 * PITCH)          /* 10240 */
#define STAGE_SZ (3 * TILE_SZ)         /* 30720: Ah,Al,Bh */
#define SMEM_GEMM (2 * STAGE_SZ)       /* 61440 -> 2 CTAs/SM */
#define NSLAB (DIMW / BK)              /* 32 */

/* attention smem layout (dynamic): K hi [128][64]f16, V^T hi [64][128]f16 */
#define PK   144
#define PV   272
#define KH0  0
#define VH0  (128 * PK)                /* 18432 */
#define SMEM_ATTN (VH0 + 64 * PV)      /* 35840 */

/* Scratch (allocation-free rule: device globals) */
__device__ float g_q[MROWS * DIMW];
__device__ float g_k[MROWS * DIMW];
__device__ float g_v[MROWS * DIMW];
__device__ __half g_xh[MROWS * DIMW];
__device__ __half g_xl[MROWS * DIMW];
__device__ __half g_ah[MROWS * DIMW];
__device__ __half g_al[MROWS * DIMW];
__device__ __half g_wh[4 * DIMW * DIMW];

/* ---------------- helpers ---------------- */
__device__ __forceinline__ uint32_t smem_u32(const void* p) {
    uint32_t a;
    asm("{ .reg .u64 t; cvta.to.shared.u64 t, %1; cvt.u32.u64 %0, t; }"
        : "=r"(a) : "l"(p));
    return a;
}
__device__ __forceinline__ void cp16(uint32_t dst, const void* src) {
    asm volatile("cp.async.cg.shared.global [%0], [%1], 16;"
                 :: "r"(dst), "l"(src) : "memory");
}
__device__ __forceinline__ void mma_f16(float* d, const uint32_t* a,
                                        const uint32_t* b) {
    asm volatile(
        "mma.sync.aligned.m16n8k16.row.col.f32.f16.f16.f32 "
        "{%0,%1,%2,%3}, {%4,%5,%6,%7}, {%8,%9}, {%0,%1,%2,%3};"
        : "+f"(d[0]), "+f"(d[1]), "+f"(d[2]), "+f"(d[3])
        : "r"(a[0]), "r"(a[1]), "r"(a[2]), "r"(a[3]), "r"(b[0]), "r"(b[1]));
}
__device__ __forceinline__ void split2h(float x, float y,
                                        uint32_t& hi, uint32_t& lo) {
    __half hx = __float2half(x);
    __half hy = __float2half(y);
    __half lx = __float2half(x - __half2float(hx));
    __half ly = __float2half(y - __half2float(hy));
    __half2 h = __halves2half2(hx, hy);
    __half2 l = __halves2half2(lx, ly);
    hi = *reinterpret_cast<uint32_t*>(&h);
    lo = *reinterpret_cast<uint32_t*>(&l);
}
__device__ __forceinline__ uint32_t pack2h(float x, float y) {
    __half2 h = __floats2half2_rn(x, y);
    return *reinterpret_cast<uint32_t*>(&h);
}

/* ---------------- fp32 -> fp16 hi/lo split (for A-side data) ---------------- */
__global__ void __launch_bounds__(256) split_kernel(
        const float* __restrict__ s,
        __half* __restrict__ dh, __half* __restrict__ dl, int n4) {
    const int i = blockIdx.x * 256 + threadIdx.x;
    if (i >= n4) return;
    float4 v = ((const float4*)s)[i];
    uint32_t h0, l0, h1, l1;
    split2h(v.x, v.y, h0, l0);
    split2h(v.z, v.w, h1, l1);
    ((uint32_t*)dh)[2*i] = h0; ((uint32_t*)dh)[2*i+1] = h1;
    ((uint32_t*)dl)[2*i] = l0; ((uint32_t*)dl)[2*i+1] = l1;
}

/* ---------------- fp32 -> fp16 (hi only, for weights B-side) ---------------- */
__global__ void __launch_bounds__(256) convh_kernel(
        const float* __restrict__ s, __half* __restrict__ dh, int n4) {
    const int i = blockIdx.x * 256 + threadIdx.x;
    if (i >= n4) return;
    float4 v = ((const float4*)s)[i];
    uint2 o;
    o.x = pack2h(v.x, v.y);
    o.y = pack2h(v.z, v.w);
    ((uint2*)dh)[i] = o;
}

/* ---------------- HMMA GEMM: C[M,N] = (Ah+Al)*Bh^T + bias ---------------- */
__device__ void gemm_mma(const __half* __restrict__ Ah,
                         const __half* __restrict__ Al,
                         const __half* __restrict__ Bh,
                         const float* __restrict__ bias,
                         float* __restrict__ C) {
    extern __shared__ char smem[];
    const uint32_t sb = smem_u32(smem);
    const int tid  = threadIdx.x;
    const int wid  = tid >> 5, lane = tid & 31;
    const int g    = lane >> 2, tig = lane & 3;
    const int wm   = (wid & 1) * 64;
    const int wn   = (wid >> 1) * 32;
    const int row0 = blockIdx.y * BM;
    const int col0 = blockIdx.x * BN;

    const __half* srcs[3] = {
        Ah + (size_t)row0 * DIMW, Al + (size_t)row0 * DIMW,
        Bh + (size_t)col0 * DIMW };

    const int r0 = tid >> 2, cc0 = (tid & 3);
    const int r1 = (tid + 256) >> 2, cc1 = ((tid + 256) & 3);

#define LOAD_STAGE(s, stg) do {                                              \
        const int k0_ = (s) * BK;                                            \
        _Pragma("unroll")                                                    \
        for (int t_ = 0; t_ < 3; ++t_) {                                     \
            const __half* b_ = srcs[t_];                                     \
            const uint32_t d_ = sb + (stg) * STAGE_SZ + t_ * TILE_SZ;        \
            cp16(d_ + r0 * PITCH + cc0 * 16,                                 \
                 b_ + (size_t)r0 * DIMW + k0_ + cc0 * 8);                    \
            cp16(d_ + r1 * PITCH + cc1 * 16,                                 \
                 b_ + (size_t)r1 * DIMW + k0_ + cc1 * 8);                    \
        }                                                                    \
    } while (0)

    float acc[4][4][4];
#pragma unroll
    for (int mi = 0; mi < 4; ++mi)
#pragma unroll
        for (int ni = 0; ni < 4; ++ni)
#pragma unroll
            for (int r = 0; r < 4; ++r) acc[mi][ni][r] = 0.f;

    LOAD_STAGE(0, 0);
    asm volatile("cp.async.commit_group;" ::: "memory");

    for (int s = 0; s < NSLAB; ++s) {
        const int cur = s & 1;
        if (s + 1 < NSLAB) {
            LOAD_STAGE(s + 1, cur ^ 1);
            asm volatile("cp.async.commit_group;" ::: "memory");
            asm volatile("cp.async.wait_group 1;" ::: "memory");
        } else {
            asm volatile("cp.async.wait_group 0;" ::: "memory");
        }
        __syncthreads();

        const char* st  = smem + cur * STAGE_SZ;
        const char* tAh = st;
        const char* tAl = st + TILE_SZ;
        const char* tBh = st + 2 * TILE_SZ;

#pragma unroll
        for (int ks = 0; ks < 2; ++ks) {
            const int kb = ks * 32 + tig * 4;
            uint32_t ah[4][4], al[4][4], bh[4][2];
#pragma unroll
            for (int mi = 0; mi < 4; ++mi) {
                const int r = wm + mi * 16 + g;
                ah[mi][0] = *(const uint32_t*)(tAh + r * PITCH + kb);
                ah[mi][1] = *(const uint32_t*)(tAh + (r + 8) * PITCH + kb);
                ah[mi][2] = *(const uint32_t*)(tAh + r * PITCH + kb + 16);
                ah[mi][3] = *(const uint32_t*)(tAh + (r + 8) * PITCH + kb + 16);
                al[mi][0] = *(const uint32_t*)(tAl + r * PITCH + kb);
                al[mi][1] = *(const uint32_t*)(tAl + (r + 8) * PITCH + kb);
                al[mi][2] = *(const uint32_t*)(tAl + r * PITCH + kb + 16);
                al[mi][3] = *(const uint32_t*)(tAl + (r + 8) * PITCH + kb + 16);
            }
#pragma unroll
            for (int ni = 0; ni < 4; ++ni) {
                const int r = wn + ni * 8 + g;
                bh[ni][0] = *(const uint32_t*)(tBh + r * PITCH + kb);
                bh[ni][1] = *(const uint32_t*)(tBh + r * PITCH + kb + 16);
            }
#pragma unroll
            for (int mi = 0; mi < 4; ++mi)
#pragma unroll
                for (int ni = 0; ni < 4; ++ni) {
                    mma_f16(acc[mi][ni], ah[mi], bh[ni]);
                    mma_f16(acc[mi][ni], al[mi], bh[ni]);
                }
        }
        __syncthreads();
    }

    /* epilogue: + bias -> C */
#pragma unroll
    for (int ni = 0; ni < 4; ++ni) {
        const int cc = col0 + wn + ni * 8 + tig * 2;
        const float b0 = bias[cc], b1 = bias[cc + 1];
#pragma unroll
        for (int mi = 0; mi < 4; ++mi) {
            const int rr = row0 + wm + mi * 16 + g;
            float2 v0, v1;
            v0.x = acc[mi][ni][0] + b0; v0.y = acc[mi][ni][1] + b1;
            v1.x = acc[mi][ni][2] + b0; v1.y = acc[mi][ni][3] + b1;
            *(float2*)(C + (size_t)rr * DIMW + cc) = v0;
            *(float2*)(C + (size_t)(rr + 8) * DIMW + cc) = v1;
        }
    }
#undef LOAD_STAGE
}

__global__ void __launch_bounds__(256, 2) qkv_tc_kernel(
        const float* __restrict__ bq, const float* __restrict__ bk,
        const float* __restrict__ bv) {
    const int z = blockIdx.z;
    const __half* Bh = g_wh + (size_t)z * DIMW * DIMW;
    const float* bias = (z == 0) ? bq : (z == 1) ? bk : bv;
    float* C = (z == 0) ? g_q : (z == 1) ? g_k : g_v;
    gemm_mma(g_xh, g_xl, Bh, bias, C);
}

__global__ void __launch_bounds__(256, 2) out_tc_kernel(
        const float* __restrict__ bo, float* __restrict__ out) {
    gemm_mma(g_ah, g_al, g_wh + (size_t)3 * DIMW * DIMW, bo, out);
}

/* ---------------- RMSNorm + interleaved RoPE (in place) ---------------- */
__global__ void __launch_bounds__(256) normrope_kernel(
        const float* __restrict__ freqs,
        const float* __restrict__ qw, const float* __restrict__ kw) {
    const int lane = threadIdx.x & 31;
    const int warp = threadIdx.x >> 5;
    const unsigned rowIdx = blockIdx.x * 8u + warp;
    float*       base = (blockIdx.y == 0) ? g_q : g_k;
    const float* w    = (blockIdx.y == 0) ? qw : kw;

    const unsigned bs = rowIdx >> 4;
    const unsigned h  = rowIdx & 15;
    const unsigned s  = bs & (S_LEN - 1);

    float* p = base + (size_t)bs * DIMW + h * HDIM + 2 * lane;
    float2 xv = *(const float2*)p;

    float ss = xv.x * xv.x + xv.y * xv.y;
#pragma unroll
    for (int off = 16; off; off >>= 1)
        ss += __shfl_xor_sync(0xffffffffu, ss, off);
    const float r = rsqrtf(ss * (1.0f / 64.0f) + 1e-6f);

    const float n0 = xv.x * r * w[2 * lane];
    const float n1 = xv.y * r * w[2 * lane + 1];

    const float f = freqs[(size_t)s * HDIM + 2 * lane];
    float sn, c;
    sincosf(f, &sn, &c);

    float2 o;
    o.x = n0 * c - n1 * sn;
    o.y = n1 * c + n0 * sn;
    *(float2*)p = o;
}

/* ---------------- HMMA chunked attention (fp16 2-term) ---------------- */
/* S = (Qh+Ql)Kh^T ; O += (Ph+Pl)Vh.  No online max (|logit|<=8).      */
__global__ void __launch_bounds__(256) attn_kernel() {
    extern __shared__ char sm[];
    const int qc  = blockIdx.x;
    const int h   = blockIdx.y;
    const int b   = blockIdx.z;
    const int tid = threadIdx.x;
    const int wid = tid >> 5, lane = tid & 31;
    const int g   = lane >> 2, tig = lane & 3;
    const int wm  = wid * 16;

    const float* qbase = g_q + ((size_t)(b * S_LEN + qc * 128)) * DIMW + h * HDIM;
    uint32_t qh[4][4], ql[4][4];
#pragma unroll
    for (int t = 0; t < 4; ++t) {
        const float* p0 = qbase + (size_t)(wm + g) * DIMW + t * 16 + 2 * tig;
        const float* p1 = qbase + (size_t)(wm + g + 8) * DIMW + t * 16 + 2 * tig;
        float2 v;
        v = *(const float2*)p0;       split2h(v.x, v.y, qh[t][0], ql[t][0]);
        v = *(const float2*)p1;       split2h(v.x, v.y, qh[t][1], ql[t][1]);
        v = *(const float2*)(p0 + 8); split2h(v.x, v.y, qh[t][2], ql[t][2]);
        v = *(const float2*)(p1 + 8); split2h(v.x, v.y, qh[t][3], ql[t][3]);
    }

    float O[8][4];
#pragma unroll
    for (int dt = 0; dt < 8; ++dt)
#pragma unroll
        for (int r = 0; r < 4; ++r) O[dt][r] = 0.f;
    float l0 = 0.f, l1 = 0.f;

    int kcs[6];
    int nkc = 0;
    kcs[nkc++] = qc;
    if (qc >= 9) {
        int lo = qc - 13; if (lo < 0) lo = 0;
        for (int ck = lo; ck <= qc - 9; ++ck) kcs[nkc++] = ck;
    }

    for (int ci = 0; ci < nkc; ++ci) {
        const size_t krow0 = (size_t)b * S_LEN + kcs[ci] * 128;
        const float* kb = g_k + krow0 * DIMW + h * HDIM;
        const float* vb = g_v + krow0 * DIMW + h * HDIM;

        __syncthreads();
        /* K chunk -> smem fp16 hi, [j][d] */
#pragma unroll
        for (int i = 0; i < 8; ++i) {
            const int idx = tid + 256 * i;
            const int j = idx >> 4, dc = (idx & 15) * 4;
            float4 v = *(const float4*)(kb + (size_t)j * DIMW + dc);
            uint2 hh;
            hh.x = pack2h(v.x, v.y);
            hh.y = pack2h(v.z, v.w);
            *(uint2*)(sm + KH0 + j * PK + dc * 2) = hh;
        }
        /* V chunk -> smem transposed [d][j] fp16 hi */
#pragma unroll
        for (int i = 0; i < 8; ++i) {
            const int idx = tid + 256 * i;
            const int j = idx >> 4, dc = (idx & 15) * 4;
            float4 v = *(const float4*)(vb + (size_t)j * DIMW + dc);
            const float vv[4] = {v.x, v.y, v.z, v.w};
#pragma unroll
            for (int e = 0; e < 4; ++e) {
                const int d = dc + e;
                *(__half*)(sm + VH0 + d * PV + j * 2) = __float2half(vv[e]);
            }
        }
        __syncthreads();

        /* ---- S = Q K^T (2-term) ---- */
        float S[16][4];
#pragma unroll
        for (int nt = 0; nt < 16; ++nt) {
            S[nt][0] = S[nt][1] = S[nt][2] = S[nt][3] = 0.f;
            const int jr = nt * 8 + g;
            uint32_t kh[4][2];
#pragma unroll
            for (int t = 0; t < 4; ++t) {
                const int ofs = jr * PK + t * 32 + tig * 4;
                kh[t][0] = *(const uint32_t*)(sm + KH0 + ofs);
                kh[t][1] = *(const uint32_t*)(sm + KH0 + ofs + 16);
            }
#pragma unroll
            for (int t = 0; t < 4; ++t) {
                mma_f16(S[nt], qh[t], kh[t]);
                mma_f16(S[nt], ql[t], kh[t]);
            }
        }

        /* ---- softmax (no max-subtract) ---- */
        float rs0 = 0.f, rs1 = 0.f;
#pragma unroll
        for (int nt = 0; nt < 16; ++nt) {
            S[nt][0] = __expf(S[nt][0] * 0.125f);
            S[nt][1] = __expf(S[nt][1] * 0.125f);
            S[nt][2] = __expf(S[nt][2] * 0.125f);
            S[nt][3] = __expf(S[nt][3] * 0.125f);
            rs0 += S[nt][0] + S[nt][1];
            rs1 += S[nt][2] + S[nt][3];
        }
        rs0 += __shfl_xor_sync(0xffffffffu, rs0, 1);
        rs0 += __shfl_xor_sync(0xffffffffu, rs0, 2);
        rs1 += __shfl_xor_sync(0xffffffffu, rs1, 1);
        rs1 += __shfl_xor_sync(0xffffffffu, rs1, 2);
        l0 += rs0;
        l1 += rs1;

        /* ---- O += P V (2-term) ---- */
#pragma unroll
        for (int tp = 0; tp < 8; ++tp) {
            uint32_t ph[4], pl[4];
            split2h(S[2*tp][0],   S[2*tp][1],   ph[0], pl[0]);
            split2h(S[2*tp][2],   S[2*tp][3],   ph[1], pl[1]);
            split2h(S[2*tp+1][0], S[2*tp+1][1], ph[2], pl[2]);
            split2h(S[2*tp+1][2], S[2*tp+1][3], ph[3], pl[3]);
#pragma unroll
            for (int dt = 0; dt < 8; ++dt) {
                const int ofs = (dt * 8 + g) * PV + tp * 32 + tig * 4;
                uint32_t bh[2];
                bh[0] = *(const uint32_t*)(sm + VH0 + ofs);
                bh[1] = *(const uint32_t*)(sm + VH0 + ofs + 16);
                mma_f16(O[dt], ph, bh);
                mma_f16(O[dt], pl, bh);
            }
        }
    }

    /* ---- epilogue: /l, write fp16 hi/lo for out-proj ---- */
    const float il0 = 1.f / l0, il1 = 1.f / l1;
    const size_t row0 = (size_t)b * S_LEN + qc * 128 + wm + g;
    const size_t base0 = row0 * DIMW + h * HDIM;
    const size_t base1 = (row0 + 8) * DIMW + h * HDIM;
#pragma unroll
    for (int dt = 0; dt < 8; ++dt) {
        const int d = dt * 8 + 2 * tig;
        uint32_t hh, ll;
        split2h(O[dt][0] * il0, O[dt][1] * il0, hh, ll);
        *(uint32_t*)(g_ah + base0 + d) = hh;
        *(uint32_t*)(g_al + base0 + d) = ll;
        split2h(O[dt][2] * il1, O[dt][3] * il1, hh, ll);
        *(uint32_t*)(g_ah + base1 + d) = hh;
        *(uint32_t*)(g_al + base1 + d) = ll;
    }
}

/* ------------------------------------------------------------------ */
extern "C" void kernel_launch(void* const* d_in, const int* in_sizes, int n_in,
                              void* d_out, int out_size) {
    const float* x     = (const float*)d_in[0];
    const float* freqs = (const float*)d_in[2];
    const float* Wq    = (const float*)d_in[3];
    const float* bq    = (const float*)d_in[4];
    const float* Wk    = (const float*)d_in[5];
    const float* bk    = (const float*)d_in[6];
    const float* Wv    = (const float*)d_in[7];
    const float* bv    = (const float*)d_in[8];
    const float* Wo    = (const float*)d_in[9];
    const float* bo    = (const float*)d_in[10];
    const float* qw    = (const float*)d_in[11];
    const float* kw    = (const float*)d_in[12];
    float* out = (float*)d_out;

    cudaFuncSetAttribute(qkv_tc_kernel,
                         cudaFuncAttributeMaxDynamicSharedMemorySize, SMEM_GEMM);
    cudaFuncSetAttribute(out_tc_kernel,
                         cudaFuncAttributeMaxDynamicSharedMemorySize, SMEM_GEMM);
    cudaFuncSetAttribute(attn_kernel,
                         cudaFuncAttributeMaxDynamicSharedMemorySize, SMEM_ATTN);

    __half *xh, *xl, *wh;
    cudaGetSymbolAddress((void**)&xh, g_xh);
    cudaGetSymbolAddress((void**)&xl, g_xl);
    cudaGetSymbolAddress((void**)&wh, g_wh);

    const int WN = DIMW * DIMW;          /* 1048576 */
    split_kernel<<<(MROWS * DIMW / 4 + 255) / 256, 256>>>(x, xh, xl, MROWS * DIMW / 4);
    convh_kernel<<<(WN / 4 + 255) / 256, 256>>>(Wq, wh + 0 * (size_t)WN, WN / 4);
    convh_kernel<<<(WN / 4 + 255) / 256, 256>>>(Wk, wh + 1 * (size_t)WN, WN / 4);
    convh_kernel<<<(WN / 4 + 255) / 256, 256>>>(Wv, wh + 2 * (size_t)WN, WN / 4);
    convh_kernel<<<(WN / 4 + 255) / 256, 256>>>(Wo, wh + 3 * (size_t)WN, WN / 4);

    qkv_tc_kernel<<<dim3(DIMW / BN, MROWS / BM, 3), 256, SMEM_GEMM>>>(bq, bk, bv);
    normrope_kernel<<<dim3((MROWS * NHEAD) / 8, 2), 256>>>(freqs, qw, kw);
    attn_kernel<<<dim3(16, NHEAD, BATCH), 256, SMEM_ATTN>>>();
    out_tc_kernel<<<dim3(DIMW / BN, MROWS / BM), 256, SMEM_GEMM>>>(bo, out);
}

// round 17
// speedup vs baseline: 1.5520x; 1.0584x over previous
#include <cuda_runtime.h>
#include <cuda_fp16.h>
#include <stdint.h>
#include <math.h>

#define S_LEN 2048
#define BATCH 2
#define DIMW  1024
#define NHEAD 16
#define HDIM  64
#define MROWS (BATCH * S_LEN)   /* 4096 */
#define WN    (DIMW * DIMW)

/* GEMM tiling (mma.sync m16n8k16 f16, 2-term split: (Ah+Al)*Bh) */
#define BM 128
#define BN 128
#define BK 32
#define PITCH 80                       /* smem row pitch: 64B data + 16B pad */
#define TILE_SZ (128 * PITCH)          /* 10240 */
#define STAGE_SZ (3 * TILE_SZ)         /* 30720: Ah,Al,Bh */
#define SMEM_GEMM (2 * STAGE_SZ)       /* 61440 -> 2 CTAs/SM */
#define NSLAB (DIMW / BK)              /* 32 */

/* attention smem layout (dynamic): K hi [128][64]f16, V^T hi [64][128]f16 */
#define PK   144
#define PV   272
#define KH0  0
#define VH0  (128 * PK)                /* 18432 */
#define SMEM_ATTN (VH0 + 64 * PV)      /* 35840 */

/* Scratch (allocation-free rule: device globals) */
__device__ __half g_xh[MROWS * DIMW];
__device__ __half g_xl[MROWS * DIMW];
__device__ __half g_qh[MROWS * DIMW];
__device__ __half g_ql[MROWS * DIMW];
__device__ __half g_kh[MROWS * DIMW];
__device__ __half g_vh[MROWS * DIMW];
__device__ __half g_ah[MROWS * DIMW];
__device__ __half g_al[MROWS * DIMW];
__device__ __half g_wh[4 * WN];
__device__ float2 g_cs[S_LEN * 32];    /* (cos,sin) per (s, headdim-pair) */

/* ---------------- helpers ---------------- */
__device__ __forceinline__ uint32_t smem_u32(const void* p) {
    uint32_t a;
    asm("{ .reg .u64 t; cvta.to.shared.u64 t, %1; cvt.u32.u64 %0, t; }"
        : "=r"(a) : "l"(p));
    return a;
}
__device__ __forceinline__ void cp16(uint32_t dst, const void* src) {
    asm volatile("cp.async.cg.shared.global [%0], [%1], 16;"
                 :: "r"(dst), "l"(src) : "memory");
}
__device__ __forceinline__ void mma_f16(float* d, const uint32_t* a,
                                        const uint32_t* b) {
    asm volatile(
        "mma.sync.aligned.m16n8k16.row.col.f32.f16.f16.f32 "
        "{%0,%1,%2,%3}, {%4,%5,%6,%7}, {%8,%9}, {%0,%1,%2,%3};"
        : "+f"(d[0]), "+f"(d[1]), "+f"(d[2]), "+f"(d[3])
        : "r"(a[0]), "r"(a[1]), "r"(a[2]), "r"(a[3]), "r"(b[0]), "r"(b[1]));
}
__device__ __forceinline__ void split2h(float x, float y,
                                        uint32_t& hi, uint32_t& lo) {
    __half hx = __float2half(x);
    __half hy = __float2half(y);
    __half lx = __float2half(x - __half2float(hx));
    __half ly = __float2half(y - __half2float(hy));
    __half2 h = __halves2half2(hx, hy);
    __half2 l = __halves2half2(lx, ly);
    hi = *reinterpret_cast<uint32_t*>(&h);
    lo = *reinterpret_cast<uint32_t*>(&l);
}
__device__ __forceinline__ uint32_t pack2h(float x, float y) {
    __half2 h = __floats2half2_rn(x, y);
    return *reinterpret_cast<uint32_t*>(&h);
}

/* ---------------- prep kernels ---------------- */
__global__ void __launch_bounds__(256) split_kernel(
        const float* __restrict__ s,
        __half* __restrict__ dh, __half* __restrict__ dl, int n4) {
    const int i = blockIdx.x * 256 + threadIdx.x;
    if (i >= n4) return;
    float4 v = ((const float4*)s)[i];
    uint32_t h0, l0, h1, l1;
    split2h(v.x, v.y, h0, l0);
    split2h(v.z, v.w, h1, l1);
    ((uint32_t*)dh)[2*i] = h0; ((uint32_t*)dh)[2*i+1] = h1;
    ((uint32_t*)dl)[2*i] = l0; ((uint32_t*)dl)[2*i+1] = l1;
}

__global__ void __launch_bounds__(256) convh4_kernel(
        const float* __restrict__ w0, const float* __restrict__ w1,
        const float* __restrict__ w2, const float* __restrict__ w3,
        int n4each) {
    const int i = blockIdx.x * 256 + threadIdx.x;
    if (i >= 4 * n4each) return;
    const int which = i / n4each, r = i - which * n4each;
    const float* s = (which == 0) ? w0 : (which == 1) ? w1
                   : (which == 2) ? w2 : w3;
    float4 v = ((const float4*)s)[r];
    uint2 o;
    o.x = pack2h(v.x, v.y);
    o.y = pack2h(v.z, v.w);
    ((uint2*)(g_wh + (size_t)which * WN))[r] = o;
}

__global__ void __launch_bounds__(256) cs_kernel(const float* __restrict__ freqs) {
    const int idx = blockIdx.x * 256 + threadIdx.x;   /* S_LEN*32 */
    const int s = idx >> 5, i = idx & 31;
    const float f = freqs[s * HDIM + 2 * i];
    float sn, c;
    sincosf(f, &sn, &c);
    g_cs[idx] = make_float2(c, sn);
}

/* ---------------- HMMA GEMM: C[M,N] = (Ah+Al)*Bh^T + bias ----------------
   Warp tile 32(M) x 64(N): each warp owns full head-rows (head = 64 cols),
   so RMSNorm's row reduction is an intra-quartet shfl.
   mode 0: fp32 +bias -> Cf      (out projection)
   mode 1: +bias, RMSNorm(w), RoPE -> Ch (+Cl if non-null)   (q / k)
   mode 2: +bias -> Ch fp16                                   (v)          */
__device__ void gemm_mma(const __half* __restrict__ Ah,
                         const __half* __restrict__ Al,
                         const __half* __restrict__ Bh,
                         const float* __restrict__ bias,
                         int mode, float* __restrict__ Cf,
                         __half* __restrict__ Ch, __half* __restrict__ Cl,
                         const float* __restrict__ w) {
    extern __shared__ char smem[];
    const uint32_t sb = smem_u32(smem);
    const int tid  = threadIdx.x;
    const int wid  = tid >> 5, lane = tid & 31;
    const int g    = lane >> 2, tig = lane & 3;
    const int wm   = (wid & 3) * 32;          /* 4 warp rows of 32 */
    const int wn   = (wid >> 2) * 64;         /* 2 warp cols of 64 */
    const int row0 = blockIdx.y * BM;
    const int col0 = blockIdx.x * BN;

    const __half* srcs[3] = {
        Ah + (size_t)row0 * DIMW, Al + (size_t)row0 * DIMW,
        Bh + (size_t)col0 * DIMW };

    const int r0 = tid >> 2, cc0 = (tid & 3);
    const int r1 = (tid + 256) >> 2, cc1 = ((tid + 256) & 3);

#define LOAD_STAGE(s, stg) do {                                              \
        const int k0_ = (s) * BK;                                            \
        _Pragma("unroll")                                                    \
        for (int t_ = 0; t_ < 3; ++t_) {                                     \
            const __half* b_ = srcs[t_];                                     \
            const uint32_t d_ = sb + (stg) * STAGE_SZ + t_ * TILE_SZ;        \
            cp16(d_ + r0 * PITCH + cc0 * 16,                                 \
                 b_ + (size_t)r0 * DIMW + k0_ + cc0 * 8);                    \
            cp16(d_ + r1 * PITCH + cc1 * 16,                                 \
                 b_ + (size_t)r1 * DIMW + k0_ + cc1 * 8);                    \
        }                                                                    \
    } while (0)

    float acc[2][8][4];
#pragma unroll
    for (int mi = 0; mi < 2; ++mi)
#pragma unroll
        for (int ni = 0; ni < 8; ++ni)
#pragma unroll
            for (int r = 0; r < 4; ++r) acc[mi][ni][r] = 0.f;

    LOAD_STAGE(0, 0);
    asm volatile("cp.async.commit_group;" ::: "memory");

    for (int s = 0; s < NSLAB; ++s) {
        const int cur = s & 1;
        if (s + 1 < NSLAB) {
            LOAD_STAGE(s + 1, cur ^ 1);
            asm volatile("cp.async.commit_group;" ::: "memory");
            asm volatile("cp.async.wait_group 1;" ::: "memory");
        } else {
            asm volatile("cp.async.wait_group 0;" ::: "memory");
        }
        __syncthreads();

        const char* st  = smem + cur * STAGE_SZ;
        const char* tAh = st;
        const char* tAl = st + TILE_SZ;
        const char* tBh = st + 2 * TILE_SZ;

#pragma unroll
        for (int ks = 0; ks < 2; ++ks) {
            const int kb = ks * 32 + tig * 4;
            uint32_t ah[2][4], al[2][4], bh[8][2];
#pragma unroll
            for (int mi = 0; mi < 2; ++mi) {
                const int r = wm + mi * 16 + g;
                ah[mi][0] = *(const uint32_t*)(tAh + r * PITCH + kb);
                ah[mi][1] = *(const uint32_t*)(tAh + (r + 8) * PITCH + kb);
                ah[mi][2] = *(const uint32_t*)(tAh + r * PITCH + kb + 16);
                ah[mi][3] = *(const uint32_t*)(tAh + (r + 8) * PITCH + kb + 16);
                al[mi][0] = *(const uint32_t*)(tAl + r * PITCH + kb);
                al[mi][1] = *(const uint32_t*)(tAl + (r + 8) * PITCH + kb);
                al[mi][2] = *(const uint32_t*)(tAl + r * PITCH + kb + 16);
                al[mi][3] = *(const uint32_t*)(tAl + (r + 8) * PITCH + kb + 16);
            }
#pragma unroll
            for (int ni = 0; ni < 8; ++ni) {
                const int r = wn + ni * 8 + g;
                bh[ni][0] = *(const uint32_t*)(tBh + r * PITCH + kb);
                bh[ni][1] = *(const uint32_t*)(tBh + r * PITCH + kb + 16);
            }
#pragma unroll
            for (int mi = 0; mi < 2; ++mi)
#pragma unroll
                for (int ni = 0; ni < 8; ++ni) {
                    mma_f16(acc[mi][ni], ah[mi], bh[ni]);
                    mma_f16(acc[mi][ni], al[mi], bh[ni]);
                }
        }
        __syncthreads();
    }

    /* bias into acc (reference order: +bias before any norm) */
#pragma unroll
    for (int ni = 0; ni < 8; ++ni) {
        const int cc = col0 + wn + ni * 8 + tig * 2;
        const float b0 = bias[cc], b1 = bias[cc + 1];
#pragma unroll
        for (int mi = 0; mi < 2; ++mi) {
            acc[mi][ni][0] += b0; acc[mi][ni][1] += b1;
            acc[mi][ni][2] += b0; acc[mi][ni][3] += b1;
        }
    }

    if (mode == 0) {
#pragma unroll
        for (int ni = 0; ni < 8; ++ni) {
            const int cc = col0 + wn + ni * 8 + tig * 2;
#pragma unroll
            for (int mi = 0; mi < 2; ++mi) {
                const int rr = row0 + wm + mi * 16 + g;
                float2 v0, v1;
                v0.x = acc[mi][ni][0]; v0.y = acc[mi][ni][1];
                v1.x = acc[mi][ni][2]; v1.y = acc[mi][ni][3];
                *(float2*)(Cf + (size_t)rr * DIMW + cc) = v0;
                *(float2*)(Cf + (size_t)(rr + 8) * DIMW + cc) = v1;
            }
        }
    } else if (mode == 2) {
#pragma unroll
        for (int ni = 0; ni < 8; ++ni) {
            const int cc = col0 + wn + ni * 8 + tig * 2;
#pragma unroll
            for (int mi = 0; mi < 2; ++mi) {
                const int rr = row0 + wm + mi * 16 + g;
                *(uint32_t*)(Ch + (size_t)rr * DIMW + cc) =
                    pack2h(acc[mi][ni][0], acc[mi][ni][1]);
                *(uint32_t*)(Ch + (size_t)(rr + 8) * DIMW + cc) =
                    pack2h(acc[mi][ni][2], acc[mi][ni][3]);
            }
        }
    } else {
        /* RMSNorm + RoPE.  Each warp's 64 N-cols = one full head. */
#pragma unroll
        for (int mi = 0; mi < 2; ++mi) {
            float ss0 = 0.f, ss1 = 0.f;
#pragma unroll
            for (int ni = 0; ni < 8; ++ni) {
                ss0 += acc[mi][ni][0] * acc[mi][ni][0]
                     + acc[mi][ni][1] * acc[mi][ni][1];
                ss1 += acc[mi][ni][2] * acc[mi][ni][2]
                     + acc[mi][ni][3] * acc[mi][ni][3];
            }
            ss0 += __shfl_xor_sync(0xffffffffu, ss0, 1);
            ss0 += __shfl_xor_sync(0xffffffffu, ss0, 2);
            ss1 += __shfl_xor_sync(0xffffffffu, ss1, 1);
            ss1 += __shfl_xor_sync(0xffffffffu, ss1, 2);
            const float rn0 = rsqrtf(ss0 * (1.0f / 64.0f) + 1e-6f);
            const float rn1 = rsqrtf(ss1 * (1.0f / 64.0f) + 1e-6f);

            const int rr = row0 + wm + mi * 16 + g;
            const int s0 = rr & (S_LEN - 1);
            const int s1 = (rr + 8) & (S_LEN - 1);
#pragma unroll
            for (int ni = 0; ni < 8; ++ni) {
                const int cc = col0 + wn + ni * 8 + tig * 2;
                const int d  = cc & 63;
                const float w0 = w[d], w1 = w[d + 1];
                const float2 cs0 = g_cs[s0 * 32 + (d >> 1)];
                const float2 cs1 = g_cs[s1 * 32 + (d >> 1)];

                float n0 = acc[mi][ni][0] * rn0 * w0;
                float n1 = acc[mi][ni][1] * rn0 * w1;
                float ox = n0 * cs0.x - n1 * cs0.y;
                float oy = n1 * cs0.x + n0 * cs0.y;
                if (Cl) {
                    uint32_t hh, ll;
                    split2h(ox, oy, hh, ll);
                    *(uint32_t*)(Ch + (size_t)rr * DIMW + cc) = hh;
                    *(uint32_t*)(Cl + (size_t)rr * DIMW + cc) = ll;
                } else {
                    *(uint32_t*)(Ch + (size_t)rr * DIMW + cc) = pack2h(ox, oy);
                }

                n0 = acc[mi][ni][2] * rn1 * w0;
                n1 = acc[mi][ni][3] * rn1 * w1;
                ox = n0 * cs1.x - n1 * cs1.y;
                oy = n1 * cs1.x + n0 * cs1.y;
                if (Cl) {
                    uint32_t hh, ll;
                    split2h(ox, oy, hh, ll);
                    *(uint32_t*)(Ch + (size_t)(rr + 8) * DIMW + cc) = hh;
                    *(uint32_t*)(Cl + (size_t)(rr + 8) * DIMW + cc) = ll;
                } else {
                    *(uint32_t*)(Ch + (size_t)(rr + 8) * DIMW + cc) =
                        pack2h(ox, oy);
                }
            }
        }
    }
#undef LOAD_STAGE
}

__global__ void __launch_bounds__(256, 2) qkv_tc_kernel(
        const float* __restrict__ bq, const float* __restrict__ bk,
        const float* __restrict__ bv, const float* __restrict__ qw,
        const float* __restrict__ kw) {
    const int z = blockIdx.z;
    if (z == 0)
        gemm_mma(g_xh, g_xl, g_wh, bq, 1, nullptr, g_qh, g_ql, qw);
    else if (z == 1)
        gemm_mma(g_xh, g_xl, g_wh + (size_t)WN, bk, 1, nullptr, g_kh, nullptr, kw);
    else
        gemm_mma(g_xh, g_xl, g_wh + (size_t)2 * WN, bv, 2, nullptr, g_vh,
                 nullptr, nullptr);
}

__global__ void __launch_bounds__(256, 2) out_tc_kernel(
        const float* __restrict__ bo, float* __restrict__ out) {
    gemm_mma(g_ah, g_al, g_wh + (size_t)3 * WN, bo, 0, out, nullptr, nullptr,
             nullptr);
}

/* ---------------- HMMA chunked attention (fp16 2-term) ---------------- */
__global__ void __launch_bounds__(256) attn_kernel() {
    extern __shared__ char sm[];
    const int qc  = blockIdx.x;
    const int h   = blockIdx.y;
    const int b   = blockIdx.z;
    const int tid = threadIdx.x;
    const int wid = tid >> 5, lane = tid & 31;
    const int g   = lane >> 2, tig = lane & 3;
    const int wm  = wid * 16;

    const __half* qb  = g_qh + ((size_t)(b * S_LEN + qc * 128)) * DIMW + h * HDIM;
    const __half* qlb = g_ql + ((size_t)(b * S_LEN + qc * 128)) * DIMW + h * HDIM;
    uint32_t qh[4][4], ql[4][4];
#pragma unroll
    for (int t = 0; t < 4; ++t) {
        const size_t o0 = (size_t)(wm + g) * DIMW + t * 16 + 2 * tig;
        const size_t o1 = (size_t)(wm + g + 8) * DIMW + t * 16 + 2 * tig;
        qh[t][0] = *(const uint32_t*)(qb + o0);
        qh[t][1] = *(const uint32_t*)(qb + o1);
        qh[t][2] = *(const uint32_t*)(qb + o0 + 8);
        qh[t][3] = *(const uint32_t*)(qb + o1 + 8);
        ql[t][0] = *(const uint32_t*)(qlb + o0);
        ql[t][1] = *(const uint32_t*)(qlb + o1);
        ql[t][2] = *(const uint32_t*)(qlb + o0 + 8);
        ql[t][3] = *(const uint32_t*)(qlb + o1 + 8);
    }

    float O[8][4];
#pragma unroll
    for (int dt = 0; dt < 8; ++dt)
#pragma unroll
        for (int r = 0; r < 4; ++r) O[dt][r] = 0.f;
    float l0 = 0.f, l1 = 0.f;

    int kcs[6];
    int nkc = 0;
    kcs[nkc++] = qc;
    if (qc >= 9) {
        int lo = qc - 13; if (lo < 0) lo = 0;
        for (int ck = lo; ck <= qc - 9; ++ck) kcs[nkc++] = ck;
    }

    for (int ci = 0; ci < nkc; ++ci) {
        const size_t krow0 = (size_t)b * S_LEN + kcs[ci] * 128;
        const __half* kb = g_kh + krow0 * DIMW + h * HDIM;
        const __half* vb = g_vh + krow0 * DIMW + h * HDIM;

        __syncthreads();
        /* K chunk -> smem [j][d] fp16 (direct row copy) */
#pragma unroll
        for (int i = 0; i < 4; ++i) {
            const int idx = tid + 256 * i;            /* 1024 uint4 slots */
            const int j = idx >> 3, c8 = (idx & 7) * 8;
            *(uint4*)(sm + KH0 + j * PK + c8 * 2) =
                *(const uint4*)(kb + (size_t)j * DIMW + c8);
        }
        /* V chunk -> smem transposed [d][j] fp16 */
#pragma unroll
        for (int i = 0; i < 8; ++i) {
            const int idx = tid + 256 * i;            /* 2048 uint2 slots */
            const int j = idx >> 4, dc = (idx & 15) * 4;
            uint2 v = *(const uint2*)(vb + (size_t)j * DIMW + dc);
            const __half2 p0 = *reinterpret_cast<__half2*>(&v.x);
            const __half2 p1 = *reinterpret_cast<__half2*>(&v.y);
            *(__half*)(sm + VH0 + (dc + 0) * PV + j * 2) = __low2half(p0);
            *(__half*)(sm + VH0 + (dc + 1) * PV + j * 2) = __high2half(p0);
            *(__half*)(sm + VH0 + (dc + 2) * PV + j * 2) = __low2half(p1);
            *(__half*)(sm + VH0 + (dc + 3) * PV + j * 2) = __high2half(p1);
        }
        __syncthreads();

        /* ---- S = Q K^T (2-term) ---- */
        float S[16][4];
#pragma unroll
        for (int nt = 0; nt < 16; ++nt) {
            S[nt][0] = S[nt][1] = S[nt][2] = S[nt][3] = 0.f;
            const int jr = nt * 8 + g;
            uint32_t kh[4][2];
#pragma unroll
            for (int t = 0; t < 4; ++t) {
                const int ofs = jr * PK + t * 32 + tig * 4;
                kh[t][0] = *(const uint32_t*)(sm + KH0 + ofs);
                kh[t][1] = *(const uint32_t*)(sm + KH0 + ofs + 16);
            }
#pragma unroll
            for (int t = 0; t < 4; ++t) {
                mma_f16(S[nt], qh[t], kh[t]);
                mma_f16(S[nt], ql[t], kh[t]);
            }
        }

        /* ---- softmax (no max-subtract; |logit| <= 8) ---- */
        float rs0 = 0.f, rs1 = 0.f;
#pragma unroll
        for (int nt = 0; nt < 16; ++nt) {
            S[nt][0] = __expf(S[nt][0] * 0.125f);
            S[nt][1] = __expf(S[nt][1] * 0.125f);
            S[nt][2] = __expf(S[nt][2] * 0.125f);
            S[nt][3] = __expf(S[nt][3] * 0.125f);
            rs0 += S[nt][0] + S[nt][1];
            rs1 += S[nt][2] + S[nt][3];
        }
        rs0 += __shfl_xor_sync(0xffffffffu, rs0, 1);
        rs0 += __shfl_xor_sync(0xffffffffu, rs0, 2);
        rs1 += __shfl_xor_sync(0xffffffffu, rs1, 1);
        rs1 += __shfl_xor_sync(0xffffffffu, rs1, 2);
        l0 += rs0;
        l1 += rs1;

        /* ---- O += P V (2-term) ---- */
#pragma unroll
        for (int tp = 0; tp < 8; ++tp) {
            uint32_t ph[4], pl[4];
            split2h(S[2*tp][0],   S[2*tp][1],   ph[0], pl[0]);
            split2h(S[2*tp][2],   S[2*tp][3],   ph[1], pl[1]);
            split2h(S[2*tp+1][0], S[2*tp+1][1], ph[2], pl[2]);
            split2h(S[2*tp+1][2], S[2*tp+1][3], ph[3], pl[3]);
#pragma unroll
            for (int dt = 0; dt < 8; ++dt) {
                const int ofs = (dt * 8 + g) * PV + tp * 32 + tig * 4;
                uint32_t bh[2];
                bh[0] = *(const uint32_t*)(sm + VH0 + ofs);
                bh[1] = *(const uint32_t*)(sm + VH0 + ofs + 16);
                mma_f16(O[dt], ph, bh);
                mma_f16(O[dt], pl, bh);
            }
        }
    }

    /* ---- epilogue: /l, write fp16 hi/lo for out-proj ---- */
    const float il0 = 1.f / l0, il1 = 1.f / l1;
    const size_t row0 = (size_t)b * S_LEN + qc * 128 + wm + g;
    const size_t base0 = row0 * DIMW + h * HDIM;
    const size_t base1 = (row0 + 8) * DIMW + h * HDIM;
#pragma unroll
    for (int dt = 0; dt < 8; ++dt) {
        const int d = dt * 8 + 2 * tig;
        uint32_t hh, ll;
        split2h(O[dt][0] * il0, O[dt][1] * il0, hh, ll);
        *(uint32_t*)(g_ah + base0 + d) = hh;
        *(uint32_t*)(g_al + base0 + d) = ll;
        split2h(O[dt][2] * il1, O[dt][3] * il1, hh, ll);
        *(uint32_t*)(g_ah + base1 + d) = hh;
        *(uint32_t*)(g_al + base1 + d) = ll;
    }
}

/* ------------------------------------------------------------------ */
extern "C" void kernel_launch(void* const* d_in, const int* in_sizes, int n_in,
                              void* d_out, int out_size) {
    const float* x     = (const float*)d_in[0];
    const float* freqs = (const float*)d_in[2];
    const float* Wq    = (const float*)d_in[3];
    const float* bq    = (const float*)d_in[4];
    const float* Wk    = (const float*)d_in[5];
    const float* bk    = (const float*)d_in[6];
    const float* Wv    = (const float*)d_in[7];
    const float* bv    = (const float*)d_in[8];
    const float* Wo    = (const float*)d_in[9];
    const float* bo    = (const float*)d_in[10];
    const float* qw    = (const float*)d_in[11];
    const float* kw    = (const float*)d_in[12];
    float* out = (float*)d_out;

    cudaFuncSetAttribute(qkv_tc_kernel,
                         cudaFuncAttributeMaxDynamicSharedMemorySize, SMEM_GEMM);
    cudaFuncSetAttribute(out_tc_kernel,
                         cudaFuncAttributeMaxDynamicSharedMemorySize, SMEM_GEMM);
    cudaFuncSetAttribute(attn_kernel,
                         cudaFuncAttributeMaxDynamicSharedMemorySize, SMEM_ATTN);

    __half *xh, *xl;
    cudaGetSymbolAddress((void**)&xh, g_xh);
    cudaGetSymbolAddress((void**)&xl, g_xl);

    split_kernel<<<(MROWS * DIMW / 4 + 255) / 256, 256>>>(x, xh, xl,
                                                          MROWS * DIMW / 4);
    convh4_kernel<<<(WN + 255) / 256, 256>>>(Wq, Wk, Wv, Wo, WN / 4);
    cs_kernel<<<(S_LEN * 32) / 256, 256>>>(freqs);

    qkv_tc_kernel<<<dim3(DIMW / BN, MROWS / BM, 3), 256, SMEM_GEMM>>>(
        bq, bk, bv, qw, kw);
    attn_kernel<<<dim3(16, NHEAD, BATCH), 256, SMEM_ATTN>>>();
    out_tc_kernel<<<dim3(DIMW / BN, MROWS / BM), 256, SMEM_GEMM>>>(bo, out);
}